// round 1
// baseline (speedup 1.0000x reference)
#include <cuda_runtime.h>
#include <math.h>

#define B_  2
#define S_  2048
#define DM_ 1024
#define H_  16
#define D_  64

// Scratch (no cudaMalloc allowed): q/k/v projections + attention concat, 16 MB each.
__device__ float g_q[B_ * S_ * DM_];
__device__ float g_k[B_ * S_ * DM_];
__device__ float g_v[B_ * S_ * DM_];
__device__ float g_attn[B_ * S_ * DM_];

// ---------------------------------------------------------------------------
// Generic GEMM + bias: C[M,N] = A[M,K] @ W[K,N] + bias[N]
// 64x64 block tile, 16x16 threads, 4x4 register tile, 16-deep K tiles.
// ---------------------------------------------------------------------------
__global__ void gemm_bias_k(const float* __restrict__ A, const float* __restrict__ W,
                            const float* __restrict__ bias, float* __restrict__ C,
                            int M, int N, int K) {
    __shared__ float As[64][17];   // [m][k], padded
    __shared__ float Bs[16][64];   // [k][n]
    const int tx = threadIdx.x, ty = threadIdx.y;
    const int tid = ty * 16 + tx;
    const int row0 = blockIdx.y * 64, col0 = blockIdx.x * 64;

    const int lm  = tid >> 2;          // 0..63
    const int lk4 = (tid & 3) << 2;    // 0,4,8,12
    const int lkb = tid >> 4;          // 0..15
    const int ln4 = (tid & 15) << 2;   // 0..60

    float acc[4][4];
#pragma unroll
    for (int i = 0; i < 4; i++)
#pragma unroll
        for (int j = 0; j < 4; j++) acc[i][j] = 0.f;

    for (int kt = 0; kt < K; kt += 16) {
        float4 a4 = *(const float4*)&A[(size_t)(row0 + lm) * K + kt + lk4];
        As[lm][lk4 + 0] = a4.x; As[lm][lk4 + 1] = a4.y;
        As[lm][lk4 + 2] = a4.z; As[lm][lk4 + 3] = a4.w;
        *(float4*)&Bs[lkb][ln4] = *(const float4*)&W[(size_t)(kt + lkb) * N + col0 + ln4];
        __syncthreads();
#pragma unroll
        for (int k = 0; k < 16; k++) {
            float a0 = As[ty * 4 + 0][k];
            float a1 = As[ty * 4 + 1][k];
            float a2 = As[ty * 4 + 2][k];
            float a3 = As[ty * 4 + 3][k];
            float4 b = *(const float4*)&Bs[k][tx * 4];
            acc[0][0] += a0 * b.x; acc[0][1] += a0 * b.y; acc[0][2] += a0 * b.z; acc[0][3] += a0 * b.w;
            acc[1][0] += a1 * b.x; acc[1][1] += a1 * b.y; acc[1][2] += a1 * b.z; acc[1][3] += a1 * b.w;
            acc[2][0] += a2 * b.x; acc[2][1] += a2 * b.y; acc[2][2] += a2 * b.z; acc[2][3] += a2 * b.w;
            acc[3][0] += a3 * b.x; acc[3][1] += a3 * b.y; acc[3][2] += a3 * b.z; acc[3][3] += a3 * b.w;
        }
        __syncthreads();
    }
#pragma unroll
    for (int i = 0; i < 4; i++) {
        size_t r = (size_t)(row0 + ty * 4 + i) * N + col0 + tx * 4;
#pragma unroll
        for (int j = 0; j < 4; j++)
            C[r + j] = acc[i][j] + bias[col0 + tx * 4 + j];
    }
}

// ---------------------------------------------------------------------------
// Batched logits: wts[bh, q, kk] = (q_head[q,:] . k_head[kk,:]) / 8
// Per (b,h): [2048 x 64] @ [64 x 2048]^T. Grid (S/64, S/64, B*H).
// ---------------------------------------------------------------------------
__global__ void scores_k(float* __restrict__ wts) {
    __shared__ float Qs[64][17];   // [m][k]
    __shared__ float Ks[64][17];   // [n][k]
    const int bh = blockIdx.z;
    const int b = bh / H_, h = bh % H_;
    const float* qb = g_q + (size_t)b * S_ * DM_ + h * D_;
    const float* kb = g_k + (size_t)b * S_ * DM_ + h * D_;
    const int tx = threadIdx.x, ty = threadIdx.y;
    const int tid = ty * 16 + tx;
    const int row0 = blockIdx.y * 64, col0 = blockIdx.x * 64;

    const int lm  = tid >> 2;
    const int lk4 = (tid & 3) << 2;

    float acc[4][4];
#pragma unroll
    for (int i = 0; i < 4; i++)
#pragma unroll
        for (int j = 0; j < 4; j++) acc[i][j] = 0.f;

#pragma unroll
    for (int kt = 0; kt < D_; kt += 16) {
        float4 a4 = *(const float4*)&qb[(size_t)(row0 + lm) * DM_ + kt + lk4];
        Qs[lm][lk4 + 0] = a4.x; Qs[lm][lk4 + 1] = a4.y;
        Qs[lm][lk4 + 2] = a4.z; Qs[lm][lk4 + 3] = a4.w;
        float4 k4v = *(const float4*)&kb[(size_t)(col0 + lm) * DM_ + kt + lk4];
        Ks[lm][lk4 + 0] = k4v.x; Ks[lm][lk4 + 1] = k4v.y;
        Ks[lm][lk4 + 2] = k4v.z; Ks[lm][lk4 + 3] = k4v.w;
        __syncthreads();
#pragma unroll
        for (int k = 0; k < 16; k++) {
            float a0 = Qs[ty * 4 + 0][k];
            float a1 = Qs[ty * 4 + 1][k];
            float a2 = Qs[ty * 4 + 2][k];
            float a3 = Qs[ty * 4 + 3][k];
            float b0 = Ks[tx * 4 + 0][k];
            float b1 = Ks[tx * 4 + 1][k];
            float b2 = Ks[tx * 4 + 2][k];
            float b3 = Ks[tx * 4 + 3][k];
            acc[0][0] += a0 * b0; acc[0][1] += a0 * b1; acc[0][2] += a0 * b2; acc[0][3] += a0 * b3;
            acc[1][0] += a1 * b0; acc[1][1] += a1 * b1; acc[1][2] += a1 * b2; acc[1][3] += a1 * b3;
            acc[2][0] += a2 * b0; acc[2][1] += a2 * b1; acc[2][2] += a2 * b2; acc[2][3] += a2 * b3;
            acc[3][0] += a3 * b0; acc[3][1] += a3 * b1; acc[3][2] += a3 * b2; acc[3][3] += a3 * b3;
        }
        __syncthreads();
    }
    const float scale = 0.125f;   // 1/sqrt(64)
#pragma unroll
    for (int i = 0; i < 4; i++) {
        size_t r = ((size_t)bh * S_ + row0 + ty * 4 + i) * S_ + col0 + tx * 4;
#pragma unroll
        for (int j = 0; j < 4; j++)
            wts[r + j] = acc[i][j] * scale;
    }
}

// ---------------------------------------------------------------------------
// Row softmax in place. One block = one row of 2048; values cached in regs.
// ---------------------------------------------------------------------------
__global__ void softmax_k(float* __restrict__ w) {
    __shared__ float sh[8];
    float* p = w + (size_t)blockIdx.x * S_;
    const int tid = threadIdx.x;   // 256
    float v[8];
    float m = -3.4e38f;
#pragma unroll
    for (int i = 0; i < 8; i++) { v[i] = p[tid + (i << 8)]; m = fmaxf(m, v[i]); }
#pragma unroll
    for (int o = 16; o; o >>= 1) m = fmaxf(m, __shfl_xor_sync(0xffffffffu, m, o));
    if ((tid & 31) == 0) sh[tid >> 5] = m;
    __syncthreads();
    m = sh[0];
#pragma unroll
    for (int i = 1; i < 8; i++) m = fmaxf(m, sh[i]);
    float s = 0.f;
#pragma unroll
    for (int i = 0; i < 8; i++) { v[i] = __expf(v[i] - m); s += v[i]; }
#pragma unroll
    for (int o = 16; o; o >>= 1) s += __shfl_xor_sync(0xffffffffu, s, o);
    __syncthreads();
    if ((tid & 31) == 0) sh[tid >> 5] = s;
    __syncthreads();
    s = 0.f;
#pragma unroll
    for (int i = 0; i < 8; i++) s += sh[i];
    const float inv = 1.0f / s;
#pragma unroll
    for (int i = 0; i < 8; i++) p[tid + (i << 8)] = v[i] * inv;
}

// ---------------------------------------------------------------------------
// Batched attn = weights @ V_head, written directly into concat layout g_attn.
// Per (b,h): [2048 x 2048] @ [2048 x 64]. Grid (1, S/64, B*H).
// ---------------------------------------------------------------------------
__global__ void attnv_k(const float* __restrict__ wts) {
    __shared__ float As[64][17];   // weights tile [m][k]
    __shared__ float Bs[16][64];   // v tile [k][n]
    const int bh = blockIdx.z;
    const int b = bh / H_, h = bh % H_;
    const float* wrow = wts + (size_t)bh * S_ * S_;
    const float* vb   = g_v + (size_t)b * S_ * DM_ + h * D_;
    float* ob         = g_attn + (size_t)b * S_ * DM_ + h * D_;
    const int tx = threadIdx.x, ty = threadIdx.y;
    const int tid = ty * 16 + tx;
    const int row0 = blockIdx.y * 64;

    const int lm  = tid >> 2;
    const int lk4 = (tid & 3) << 2;
    const int lkb = tid >> 4;
    const int ln4 = (tid & 15) << 2;

    float acc[4][4];
#pragma unroll
    for (int i = 0; i < 4; i++)
#pragma unroll
        for (int j = 0; j < 4; j++) acc[i][j] = 0.f;

    for (int kt = 0; kt < S_; kt += 16) {
        float4 a4 = *(const float4*)&wrow[(size_t)(row0 + lm) * S_ + kt + lk4];
        As[lm][lk4 + 0] = a4.x; As[lm][lk4 + 1] = a4.y;
        As[lm][lk4 + 2] = a4.z; As[lm][lk4 + 3] = a4.w;
        *(float4*)&Bs[lkb][ln4] = *(const float4*)&vb[(size_t)(kt + lkb) * DM_ + ln4];
        __syncthreads();
#pragma unroll
        for (int k = 0; k < 16; k++) {
            float a0 = As[ty * 4 + 0][k];
            float a1 = As[ty * 4 + 1][k];
            float a2 = As[ty * 4 + 2][k];
            float a3 = As[ty * 4 + 3][k];
            float4 bv = *(const float4*)&Bs[k][tx * 4];
            acc[0][0] += a0 * bv.x; acc[0][1] += a0 * bv.y; acc[0][2] += a0 * bv.z; acc[0][3] += a0 * bv.w;
            acc[1][0] += a1 * bv.x; acc[1][1] += a1 * bv.y; acc[1][2] += a1 * bv.z; acc[1][3] += a1 * bv.w;
            acc[2][0] += a2 * bv.x; acc[2][1] += a2 * bv.y; acc[2][2] += a2 * bv.z; acc[2][3] += a2 * bv.w;
            acc[3][0] += a3 * bv.x; acc[3][1] += a3 * bv.y; acc[3][2] += a3 * bv.z; acc[3][3] += a3 * bv.w;
        }
        __syncthreads();
    }
#pragma unroll
    for (int i = 0; i < 4; i++) {
        size_t r = (size_t)(row0 + ty * 4 + i) * DM_ + tx * 4;
#pragma unroll
        for (int j = 0; j < 4; j++)
            ob[r + j] = acc[i][j];
    }
}

// ---------------------------------------------------------------------------
extern "C" void kernel_launch(void* const* d_in, const int* in_sizes, int n_in,
                              void* d_out, int out_size) {
    const float* Qi = (const float*)d_in[0];
    const float* Ki = (const float*)d_in[1];
    const float* Vi = (const float*)d_in[2];
    const float* Wq = (const float*)d_in[3];
    const float* bq = (const float*)d_in[4];
    const float* Wk = (const float*)d_in[5];
    const float* bk = (const float*)d_in[6];
    const float* Wv = (const float*)d_in[7];
    const float* bv = (const float*)d_in[8];
    const float* Wo = (const float*)d_in[9];
    const float* bo = (const float*)d_in[10];

    float* out = (float*)d_out;                       // [B,S,DM]
    float* wts = out + (size_t)B_ * S_ * DM_;         // [B,H,S,S]

    float *gq, *gk, *gv, *ga;
    cudaGetSymbolAddress((void**)&gq, g_q);
    cudaGetSymbolAddress((void**)&gk, g_k);
    cudaGetSymbolAddress((void**)&gv, g_v);
    cudaGetSymbolAddress((void**)&ga, g_attn);

    dim3 blk(16, 16);
    dim3 gproj(DM_ / 64, (B_ * S_) / 64);             // (16, 64)

    gemm_bias_k<<<gproj, blk>>>(Qi, Wq, bq, gq, B_ * S_, DM_, DM_);
    gemm_bias_k<<<gproj, blk>>>(Ki, Wk, bk, gk, B_ * S_, DM_, DM_);
    gemm_bias_k<<<gproj, blk>>>(Vi, Wv, bv, gv, B_ * S_, DM_, DM_);

    scores_k<<<dim3(S_ / 64, S_ / 64, B_ * H_), blk>>>(wts);
    softmax_k<<<B_ * H_ * S_, 256>>>(wts);
    attnv_k<<<dim3(1, S_ / 64, B_ * H_), blk>>>(wts);

    gemm_bias_k<<<gproj, blk>>>(ga, Wo, bo, out, B_ * S_, DM_, DM_);
}